// round 1
// baseline (speedup 1.0000x reference)
#include <cuda_runtime.h>
#include <math.h>

// Problem constants
#define B_  2
#define S_  2048
#define D_  4096
#define H_  32
#define HD_ 128
#define M_  (B_*S_)   // 4096 rows for the big GEMMs

// Scratch (device globals: no allocation allowed in kernel_launch).
// q,k,v in [B,H,S,HD] layout (attention-friendly), att in [B,S,H*HD].
__device__ float g_q[B_*H_*S_*HD_];
__device__ float g_k[B_*H_*S_*HD_];
__device__ float g_v[B_*H_*S_*HD_];
__device__ float g_att[(size_t)B_*S_*D_];

// ---------------------------------------------------------------------------
// GEMM: raw[m,n] = sum_k A[m,k] * W[n,k]   (M=N=K=4096), 128x128 block tile,
// 8x8 per thread, BK=16, smem transposed with +4 pad for bank conflicts.
// EPI 0: plain store C[m*4096+n]
// EPI 1: scatter to [B,H,S,HD]
// EPI 2: scatter to [B,H,S,HD] with fused RoPE (pairs are intra-thread since
//        each thread owns 8 consecutive cols and head dim blocks are 128-aligned)
// ---------------------------------------------------------------------------
template <int EPI>
__global__ void __launch_bounds__(256, 2)
sgemm_kernel(const float* __restrict__ A, const float* __restrict__ W,
             float* __restrict__ C,
             const float* __restrict__ cosT, const float* __restrict__ sinT)
{
    constexpr int Kd = 4096;
    constexpr int Nd = 4096;
    __shared__ float as[16 * 132];
    __shared__ float bs[16 * 132];

    const int tid = threadIdx.x;
    const int bx  = blockIdx.x;   // n block
    const int by  = blockIdx.y;   // m block
    const int tx  = tid & 15;
    const int ty  = tid >> 4;
    const int lr  = tid >> 2;     // 0..63 load row (within 64-row half)
    const int lc  = tid & 3;      // which float4 of 16-wide k slice

    const float* Aptr = A + (size_t)(by * 128) * Kd + lc * 4;
    const float* Wptr = W + (size_t)(bx * 128) * Kd + lc * 4;

    float acc[8][8];
    #pragma unroll
    for (int i = 0; i < 8; i++)
        #pragma unroll
        for (int j = 0; j < 8; j++) acc[i][j] = 0.f;

    for (int kt = 0; kt < Kd; kt += 16) {
        #pragma unroll
        for (int half = 0; half < 2; half++) {
            int r = half * 64 + lr;
            float4 va = *reinterpret_cast<const float4*>(Aptr + (size_t)r * Kd + kt);
            float4 vb = *reinterpret_cast<const float4*>(Wptr + (size_t)r * Kd + kt);
            as[(lc*4+0)*132 + r] = va.x;
            as[(lc*4+1)*132 + r] = va.y;
            as[(lc*4+2)*132 + r] = va.z;
            as[(lc*4+3)*132 + r] = va.w;
            bs[(lc*4+0)*132 + r] = vb.x;
            bs[(lc*4+1)*132 + r] = vb.y;
            bs[(lc*4+2)*132 + r] = vb.z;
            bs[(lc*4+3)*132 + r] = vb.w;
        }
        __syncthreads();
        #pragma unroll
        for (int kk = 0; kk < 16; kk++) {
            float ra[8], rb[8];
            *reinterpret_cast<float4*>(&ra[0]) = *reinterpret_cast<const float4*>(&as[kk*132 + ty*8]);
            *reinterpret_cast<float4*>(&ra[4]) = *reinterpret_cast<const float4*>(&as[kk*132 + ty*8 + 4]);
            *reinterpret_cast<float4*>(&rb[0]) = *reinterpret_cast<const float4*>(&bs[kk*132 + tx*8]);
            *reinterpret_cast<float4*>(&rb[4]) = *reinterpret_cast<const float4*>(&bs[kk*132 + tx*8 + 4]);
            #pragma unroll
            for (int i = 0; i < 8; i++)
                #pragma unroll
                for (int j = 0; j < 8; j++)
                    acc[i][j] += ra[i] * rb[j];
        }
        __syncthreads();
    }

    const int n0 = bx * 128 + tx * 8;
    if (EPI == 0) {
        #pragma unroll
        for (int i = 0; i < 8; i++) {
            int m = by * 128 + ty * 8 + i;
            float* p = C + (size_t)m * Nd + n0;
            *reinterpret_cast<float4*>(p)     = make_float4(acc[i][0], acc[i][1], acc[i][2], acc[i][3]);
            *reinterpret_cast<float4*>(p + 4) = make_float4(acc[i][4], acc[i][5], acc[i][6], acc[i][7]);
        }
    } else {
        const int h = n0 >> 7;     // head index (block is 128-col aligned -> single head)
        const int d = n0 & 127;    // dim-in-head of first owned col (even)
        #pragma unroll
        for (int i = 0; i < 8; i++) {
            int m = by * 128 + ty * 8 + i;
            int b = m >> 11;
            int s = m & 2047;
            float v[8];
            #pragma unroll
            for (int j = 0; j < 8; j++) v[j] = acc[i][j];
            if (EPI == 2) {
                // RoPE on pairs (d+2jj, d+2jj+1); pair index = d/2 + jj
                #pragma unroll
                for (int jj = 0; jj < 4; jj++) {
                    float c  = cosT[s * 64 + (d >> 1) + jj];
                    float sn = sinT[s * 64 + (d >> 1) + jj];
                    float a  = acc[i][2*jj];
                    float bq = acc[i][2*jj+1];
                    v[2*jj]   = a * c  - bq * sn;
                    v[2*jj+1] = a * sn + bq * c;
                }
            }
            float* p = C + (((size_t)(b * H_ + h) * S_ + s) * HD_ + d);
            *reinterpret_cast<float4*>(p)     = make_float4(v[0], v[1], v[2], v[3]);
            *reinterpret_cast<float4*>(p + 4) = make_float4(v[4], v[5], v[6], v[7]);
        }
    }
}

// ---------------------------------------------------------------------------
// Flash-style causal attention. One block per (q-tile of 128 rows, b*h).
// Bc = 64 KV rows per iteration. 256 threads:
//   scores: thread (rg=tid/16, cg=tid%16) owns rows rg*8..+7, cols cg*4..+3
//   output: same rows, d-cols cg*8..+7
// Row-group = 16 contiguous lanes (half warp) -> shfl.xor reductions.
// smem: Q[128][132] K[64][132] V[64][132] P[128][68]  (~166 KB dynamic)
// ---------------------------------------------------------------------------
#define ATTN_SMEM_FLOATS (128*132 + 64*132 + 64*132 + 128*68)

__global__ void __launch_bounds__(256, 1)
attn_kernel(const float* __restrict__ Qg, const float* __restrict__ Kg,
            const float* __restrict__ Vg, float* __restrict__ Og)
{
    extern __shared__ float sm[];
    float* Qs = sm;                       // [128][132]
    float* Ks = Qs + 128*132;             // [64][132]
    float* Vs = Ks + 64*132;              // [64][132]
    float* Ps = Vs + 64*132;              // [128][68]

    const int tid = threadIdx.x;
    const int qt  = blockIdx.x;           // 0..15 (q tile)
    const int bh  = blockIdx.y;           // 0..63 (b*H + h)
    const int rg  = tid >> 4;
    const int cg  = tid & 15;

    const float* Qb = Qg + (size_t)bh * S_ * HD_;
    const float* Kb = Kg + (size_t)bh * S_ * HD_;
    const float* Vb = Vg + (size_t)bh * S_ * HD_;

    // Load Q tile (128x128)
    for (int idx = tid; idx < 128 * 32; idx += 256) {
        int r = idx >> 5, c4 = idx & 31;
        *reinterpret_cast<float4*>(&Qs[r*132 + c4*4]) =
            *reinterpret_cast<const float4*>(&Qb[(size_t)(qt*128 + r)*HD_ + c4*4]);
    }

    float m_i[8], l_i[8], o[8][8];
    #pragma unroll
    for (int i = 0; i < 8; i++) {
        m_i[i] = -1e30f;
        l_i[i] = 0.f;
        #pragma unroll
        for (int j = 0; j < 8; j++) o[i][j] = 0.f;
    }
    __syncthreads();

    const int nkv = 2*qt + 2;                  // causal: kv tiles 0..2qt+1
    const float scale = 0.08838834764831843f;  // 1/sqrt(128)

    for (int kt = 0; kt < nkv; kt++) {
        // Load K,V tiles (64x128 each)
        for (int idx = tid; idx < 64 * 32; idx += 256) {
            int r = idx >> 5, c4 = idx & 31;
            *reinterpret_cast<float4*>(&Ks[r*132 + c4*4]) =
                *reinterpret_cast<const float4*>(&Kb[(size_t)(kt*64 + r)*HD_ + c4*4]);
            *reinterpret_cast<float4*>(&Vs[r*132 + c4*4]) =
                *reinterpret_cast<const float4*>(&Vb[(size_t)(kt*64 + r)*HD_ + c4*4]);
        }
        __syncthreads();

        // S = Q K^T (8 rows x 4 cols per thread, k in chunks of 4)
        float sf[8][4];
        #pragma unroll
        for (int i = 0; i < 8; i++)
            #pragma unroll
            for (int j = 0; j < 4; j++) sf[i][j] = 0.f;

        for (int k = 0; k < 128; k += 4) {
            float4 kv4[4];
            #pragma unroll
            for (int j = 0; j < 4; j++)
                kv4[j] = *reinterpret_cast<const float4*>(&Ks[(cg*4 + j)*132 + k]);
            #pragma unroll
            for (int i = 0; i < 8; i++) {
                float4 q4 = *reinterpret_cast<const float4*>(&Qs[(rg*8 + i)*132 + k]);
                #pragma unroll
                for (int j = 0; j < 4; j++) {
                    sf[i][j] += q4.x*kv4[j].x + q4.y*kv4[j].y
                              + q4.z*kv4[j].z + q4.w*kv4[j].w;
                }
            }
        }

        // scale + causal mask (only diagonal tiles actually mask anything)
        const int rbase = qt*128 + rg*8;
        const int cbase = kt*64  + cg*4;
        #pragma unroll
        for (int i = 0; i < 8; i++)
            #pragma unroll
            for (int j = 0; j < 4; j++) {
                float v = sf[i][j] * scale;
                if (cbase + j > rbase + i) v = -1e30f;
                sf[i][j] = v;
            }

        // Online softmax (row stats replicated across the 16-lane row group)
        #pragma unroll
        for (int i = 0; i < 8; i++) {
            float rm = fmaxf(fmaxf(sf[i][0], sf[i][1]), fmaxf(sf[i][2], sf[i][3]));
            #pragma unroll
            for (int off = 1; off < 16; off <<= 1)
                rm = fmaxf(rm, __shfl_xor_sync(0xffffffffu, rm, off));
            float mn = fmaxf(m_i[i], rm);
            float alpha = expf(m_i[i] - mn);
            m_i[i] = mn;
            float rs = 0.f;
            #pragma unroll
            for (int j = 0; j < 4; j++) {
                float p = expf(sf[i][j] - mn);
                sf[i][j] = p;
                rs += p;
            }
            #pragma unroll
            for (int off = 1; off < 16; off <<= 1)
                rs += __shfl_xor_sync(0xffffffffu, rs, off);
            l_i[i] = l_i[i] * alpha + rs;
            #pragma unroll
            for (int j = 0; j < 8; j++) o[i][j] *= alpha;
            #pragma unroll
            for (int j = 0; j < 4; j++)
                Ps[(rg*8 + i)*68 + cg*4 + j] = sf[i][j];
        }
        __syncthreads();

        // O += P @ V  (8 rows x 8 d-cols per thread)
        for (int c = 0; c < 64; c++) {
            float4 v0 = *reinterpret_cast<const float4*>(&Vs[c*132 + cg*8]);
            float4 v1 = *reinterpret_cast<const float4*>(&Vs[c*132 + cg*8 + 4]);
            #pragma unroll
            for (int i = 0; i < 8; i++) {
                float p = Ps[(rg*8 + i)*68 + c];
                o[i][0] += p * v0.x; o[i][1] += p * v0.y;
                o[i][2] += p * v0.z; o[i][3] += p * v0.w;
                o[i][4] += p * v1.x; o[i][5] += p * v1.y;
                o[i][6] += p * v1.z; o[i][7] += p * v1.w;
            }
        }
        __syncthreads();
    }

    // Normalize and write to [B,S,H,HD] so the output GEMM reads row-major
    const int b = bh >> 5;
    const int h = bh & 31;
    #pragma unroll
    for (int i = 0; i < 8; i++) {
        float inv = 1.f / l_i[i];
        int s = qt*128 + rg*8 + i;
        float* p = Og + (((size_t)(b * S_ + s) * H_ + h) * HD_ + cg*8);
        *reinterpret_cast<float4*>(p) =
            make_float4(o[i][0]*inv, o[i][1]*inv, o[i][2]*inv, o[i][3]*inv);
        *reinterpret_cast<float4*>(p+4) =
            make_float4(o[i][4]*inv, o[i][5]*inv, o[i][6]*inv, o[i][7]*inv);
    }
}

// ---------------------------------------------------------------------------
// Launch. Inputs (metadata order): x, freqs_cos, freqs_sin, mask, wq, wk, wv,
// wo, cache_k, cache_v, start_pos.  start_pos == 0 in this problem; mask is
// pure causal -1e9 which the attention kernel reproduces exactly.
// ---------------------------------------------------------------------------
extern "C" void kernel_launch(void* const* d_in, const int* in_sizes, int n_in,
                              void* d_out, int out_size)
{
    const float* x  = (const float*)d_in[0];
    const float* fc = (const float*)d_in[1];
    const float* fs = (const float*)d_in[2];
    const float* wq = (const float*)d_in[4];
    const float* wk = (const float*)d_in[5];
    const float* wv = (const float*)d_in[6];
    const float* wo = (const float*)d_in[7];
    float* out = (float*)d_out;

    float *q, *k, *v, *att;
    cudaGetSymbolAddress((void**)&q,   g_q);
    cudaGetSymbolAddress((void**)&k,   g_k);
    cudaGetSymbolAddress((void**)&v,   g_v);
    cudaGetSymbolAddress((void**)&att, g_att);

    const size_t attn_smem = (size_t)ATTN_SMEM_FLOATS * sizeof(float);
    cudaFuncSetAttribute(attn_kernel, cudaFuncAttributeMaxDynamicSharedMemorySize,
                         (int)attn_smem);

    dim3 gg(32, 32), gb(256);
    // QKV projections (RoPE fused into q/k epilogues)
    sgemm_kernel<2><<<gg, gb>>>(x, wq, q, fc, fs);
    sgemm_kernel<2><<<gg, gb>>>(x, wk, k, fc, fs);
    sgemm_kernel<1><<<gg, gb>>>(x, wv, v, fc, fs);
    // Causal attention
    attn_kernel<<<dim3(16, 64), 256, attn_smem>>>(q, k, v, att);
    // Output projection straight into d_out
    sgemm_kernel<0><<<gg, gb>>>(att, wo, out, fc, fs);
}

// round 4
// speedup vs baseline: 1.6382x; 1.6382x over previous
#include <cuda_runtime.h>
#include <cuda_bf16.h>
#include <math.h>
#include <stdint.h>

// Problem constants
#define B_  2
#define S_  2048
#define D_  4096
#define H_  32
#define HD_ 128

// ---------------------------------------------------------------------------
// Device scratch (no allocation allowed in kernel_launch)
// ---------------------------------------------------------------------------
__device__ float g_q[B_*H_*S_*HD_];
__device__ float g_k[B_*H_*S_*HD_];
__device__ float g_v[B_*H_*S_*HD_];
__device__ float g_att[(size_t)B_*S_*D_];
__device__ __nv_bfloat16 g_xh[(size_t)D_*D_];   // A hi (x or att)
__device__ __nv_bfloat16 g_xl[(size_t)D_*D_];   // A lo
__device__ __nv_bfloat16 g_bh[(size_t)D_*D_];   // W hi (reused per GEMM)
__device__ __nv_bfloat16 g_bl[(size_t)D_*D_];   // W lo

// ---------------------------------------------------------------------------
// sm_100-safe PTX helpers (cp.async / ldmatrix / mma.sync only)
// ---------------------------------------------------------------------------
__device__ __forceinline__ void cp16(uint32_t s, const void* g) {
    asm volatile("cp.async.cg.shared.global [%0], [%1], 16;\n" :: "r"(s), "l"(g) : "memory");
}
__device__ __forceinline__ void cp_commit() {
    asm volatile("cp.async.commit_group;\n" ::: "memory");
}
template<int N> __device__ __forceinline__ void cp_wait() {
    asm volatile("cp.async.wait_group %0;\n" :: "n"(N) : "memory");
}
__device__ __forceinline__ void ldsm4(uint32_t* r, uint32_t addr) {
    asm volatile("ldmatrix.sync.aligned.m8n8.x4.shared.b16 {%0,%1,%2,%3}, [%4];"
        : "=r"(r[0]), "=r"(r[1]), "=r"(r[2]), "=r"(r[3]) : "r"(addr));
}
__device__ __forceinline__ void mma16816(float* d, const uint32_t* a,
                                         uint32_t b0, uint32_t b1) {
    asm volatile(
        "mma.sync.aligned.m16n8k16.row.col.f32.bf16.bf16.f32 "
        "{%0,%1,%2,%3}, {%4,%5,%6,%7}, {%8,%9}, {%0,%1,%2,%3};"
        : "+f"(d[0]), "+f"(d[1]), "+f"(d[2]), "+f"(d[3])
        : "r"(a[0]), "r"(a[1]), "r"(a[2]), "r"(a[3]), "r"(b0), "r"(b1));
}

// ---------------------------------------------------------------------------
// Split fp32 -> (hi bf16, lo bf16);  x ~= hi + lo to ~16 mantissa bits
// ---------------------------------------------------------------------------
__global__ void split_kernel(const float* __restrict__ src,
                             __nv_bfloat16* __restrict__ hi,
                             __nv_bfloat16* __restrict__ lo, int n4)
{
    int i = blockIdx.x * blockDim.x + threadIdx.x;
    if (i >= n4) return;
    float4 v = reinterpret_cast<const float4*>(src)[i];
    __nv_bfloat16 h0 = __float2bfloat16(v.x);
    __nv_bfloat16 h1 = __float2bfloat16(v.y);
    __nv_bfloat16 h2 = __float2bfloat16(v.z);
    __nv_bfloat16 h3 = __float2bfloat16(v.w);
    __nv_bfloat16 l0 = __float2bfloat16(v.x - __bfloat162float(h0));
    __nv_bfloat16 l1 = __float2bfloat16(v.y - __bfloat162float(h1));
    __nv_bfloat16 l2 = __float2bfloat16(v.z - __bfloat162float(h2));
    __nv_bfloat16 l3 = __float2bfloat16(v.w - __bfloat162float(h3));
    __nv_bfloat162* hp = reinterpret_cast<__nv_bfloat162*>(hi);
    __nv_bfloat162* lp = reinterpret_cast<__nv_bfloat162*>(lo);
    hp[2*i]   = __halves2bfloat162(h0, h1);
    hp[2*i+1] = __halves2bfloat162(h2, h3);
    lp[2*i]   = __halves2bfloat162(l0, l1);
    lp[2*i+1] = __halves2bfloat162(l2, l3);
}

// ---------------------------------------------------------------------------
// HMMA GEMM: C[m,n] = sum_k A[m,k]*B[n,k], M=N=K=4096, bf16x3 (hi/lo).
// CTA 128x128, BK=32, 8 warps (warp tile 64x32), 3-stage cp.async pipeline.
// Smem rows padded to 80 B -> conflict-free ldmatrix.
// EPI 0: C[m*4096+n]; EPI 1: scatter [B,H,S,HD]; EPI 2: scatter + fused RoPE.
// ---------------------------------------------------------------------------
#define NKT 128                 // 4096 / 32
#define ARR_B 10240             // 128 rows * 80 B
#define STAGE_B (4*ARR_B)       // Ah, Al, Bh, Bl
#define GEMM_SMEM (3*STAGE_B)   // 122880 B

template<int EPI>
__global__ void __launch_bounds__(256, 1)
gemm_mma(const __nv_bfloat16* __restrict__ Ah, const __nv_bfloat16* __restrict__ Al,
         const __nv_bfloat16* __restrict__ Bh, const __nv_bfloat16* __restrict__ Bl,
         float* __restrict__ C,
         const float* __restrict__ cosT, const float* __restrict__ sinT)
{
    extern __shared__ char smem[];
    const uint32_t sb = (uint32_t)__cvta_generic_to_shared(smem);
    const int tid  = threadIdx.x;
    const int wid  = tid >> 5;
    const int lane = tid & 31;
    const int m0 = blockIdx.y * 128;
    const int n0 = blockIdx.x * 128;
    const int wm = (wid >> 2) * 64;     // warp m offset (0 or 64)
    const int wn = (wid & 3) * 32;      // warp n offset (0/32/64/96)

    auto load_stage = [&](int kt, int buf) {
        const uint32_t st = sb + (uint32_t)buf * STAGE_B;
        const int k0 = kt * 32;
        for (int i = tid; i < 512; i += 256) {
            int r = i >> 2, q = i & 3;
            uint32_t so = (uint32_t)(r * 80 + q * 16);
            size_t ga = (size_t)(m0 + r) * D_ + k0 + q * 8;
            size_t gb = (size_t)(n0 + r) * D_ + k0 + q * 8;
            cp16(st + 0*ARR_B + so, Ah + ga);
            cp16(st + 1*ARR_B + so, Al + ga);
            cp16(st + 2*ARR_B + so, Bh + gb);
            cp16(st + 3*ARR_B + so, Bl + gb);
        }
    };

    float acc[4][4][4];
    #pragma unroll
    for (int mt = 0; mt < 4; mt++)
        #pragma unroll
        for (int nt = 0; nt < 4; nt++)
            #pragma unroll
            for (int e = 0; e < 4; e++) acc[mt][nt][e] = 0.f;

    load_stage(0, 0); cp_commit();
    load_stage(1, 1); cp_commit();

    for (int kt = 0; kt < NKT; kt++) {
        // Protect buffer (kt+2)%3 == (kt-1)%3: all warps must be done with kt-1.
        __syncthreads();
        if (kt + 2 < NKT) load_stage(kt + 2, (kt + 2) % 3);
        cp_commit();                      // always commit (group accounting)
        cp_wait<2>();                     // stage kt's data resident
        __syncthreads();

        const uint32_t st = sb + (uint32_t)(kt % 3) * STAGE_B;
        #pragma unroll
        for (int ks = 0; ks < 2; ks++) {
            const int ko = ks * 32 + (lane >> 4) * 16;     // byte offset in row
            uint32_t ah[4][4], al[4][4], bh[2][4], bl[2][4];
            const int rA = wm + (lane & 15);
            #pragma unroll
            for (int mt = 0; mt < 4; mt++) {
                uint32_t off = (uint32_t)((rA + mt * 16) * 80 + ko);
                ldsm4(ah[mt], st + 0*ARR_B + off);
                ldsm4(al[mt], st + 1*ARR_B + off);
            }
            const int rB = wn + (lane & 15);
            #pragma unroll
            for (int np = 0; np < 2; np++) {
                uint32_t off = (uint32_t)((rB + np * 16) * 80 + ko);
                ldsm4(bh[np], st + 2*ARR_B + off);
                ldsm4(bl[np], st + 3*ARR_B + off);
            }
            #pragma unroll
            for (int mt = 0; mt < 4; mt++)
                #pragma unroll
                for (int nt = 0; nt < 4; nt++) {
                    const int np = nt >> 1, sel = nt & 1;
                    mma16816(acc[mt][nt], ah[mt], bh[np][sel], bh[np][sel + 2]);
                    mma16816(acc[mt][nt], ah[mt], bl[np][sel], bl[np][sel + 2]);
                    mma16816(acc[mt][nt], al[mt], bh[np][sel], bh[np][sel + 2]);
                }
        }
    }

    // Epilogue: direct register stores (+ fused RoPE for EPI 2)
    #pragma unroll
    for (int mt = 0; mt < 4; mt++) {
        #pragma unroll
        for (int nt = 0; nt < 4; nt++) {
            const int mrow = m0 + wm + mt * 16 + (lane >> 2);
            const int col  = wn + nt * 8 + 2 * (lane & 3);   // 0..126, even
            #pragma unroll
            for (int hrow = 0; hrow < 2; hrow++) {
                const int m = mrow + hrow * 8;
                float e = acc[mt][nt][2*hrow], o = acc[mt][nt][2*hrow + 1];
                if (EPI == 0) {
                    float* p = &C[(size_t)m * D_ + n0 + col];
                    p[0] = e; p[1] = o;
                } else {
                    const int b = m >> 11, s = m & (S_ - 1);
                    if (EPI == 2) {
                        float cc = cosT[s * 64 + (col >> 1)];
                        float ss = sinT[s * 64 + (col >> 1)];
                        float t0 = e * cc - o * ss;
                        o = e * ss + o * cc;
                        e = t0;
                    }
                    // head = blockIdx.x (CTA n-width == HD_ == 128)
                    float* p = &C[(((size_t)(b * H_ + blockIdx.x) * S_ + s) * HD_ + col)];
                    p[0] = e; p[1] = o;
                }
            }
        }
    }
}

// ---------------------------------------------------------------------------
// Flash-style causal attention (unchanged; known-good from round 1)
// ---------------------------------------------------------------------------
#define ATTN_SMEM_FLOATS (128*132 + 64*132 + 64*132 + 128*68)

__global__ void __launch_bounds__(256, 1)
attn_kernel(const float* __restrict__ Qg, const float* __restrict__ Kg,
            const float* __restrict__ Vg, float* __restrict__ Og)
{
    extern __shared__ float sm[];
    float* Qs = sm;
    float* Ks = Qs + 128*132;
    float* Vs = Ks + 64*132;
    float* Ps = Vs + 64*132;

    const int tid = threadIdx.x;
    const int qt  = blockIdx.x;
    const int bh  = blockIdx.y;
    const int rg  = tid >> 4;
    const int cg  = tid & 15;

    const float* Qb = Qg + (size_t)bh * S_ * HD_;
    const float* Kb = Kg + (size_t)bh * S_ * HD_;
    const float* Vb = Vg + (size_t)bh * S_ * HD_;

    for (int idx = tid; idx < 128 * 32; idx += 256) {
        int r = idx >> 5, c4 = idx & 31;
        *reinterpret_cast<float4*>(&Qs[r*132 + c4*4]) =
            *reinterpret_cast<const float4*>(&Qb[(size_t)(qt*128 + r)*HD_ + c4*4]);
    }

    float m_i[8], l_i[8], o[8][8];
    #pragma unroll
    for (int i = 0; i < 8; i++) {
        m_i[i] = -1e30f; l_i[i] = 0.f;
        #pragma unroll
        for (int j = 0; j < 8; j++) o[i][j] = 0.f;
    }
    __syncthreads();

    const int nkv = 2*qt + 2;
    const float scale = 0.08838834764831843f;

    for (int kt = 0; kt < nkv; kt++) {
        for (int idx = tid; idx < 64 * 32; idx += 256) {
            int r = idx >> 5, c4 = idx & 31;
            *reinterpret_cast<float4*>(&Ks[r*132 + c4*4]) =
                *reinterpret_cast<const float4*>(&Kb[(size_t)(kt*64 + r)*HD_ + c4*4]);
            *reinterpret_cast<float4*>(&Vs[r*132 + c4*4]) =
                *reinterpret_cast<const float4*>(&Vb[(size_t)(kt*64 + r)*HD_ + c4*4]);
        }
        __syncthreads();

        float sf[8][4];
        #pragma unroll
        for (int i = 0; i < 8; i++)
            #pragma unroll
            for (int j = 0; j < 4; j++) sf[i][j] = 0.f;

        for (int k = 0; k < 128; k += 4) {
            float4 kv4[4];
            #pragma unroll
            for (int j = 0; j < 4; j++)
                kv4[j] = *reinterpret_cast<const float4*>(&Ks[(cg*4 + j)*132 + k]);
            #pragma unroll
            for (int i = 0; i < 8; i++) {
                float4 q4 = *reinterpret_cast<const float4*>(&Qs[(rg*8 + i)*132 + k]);
                #pragma unroll
                for (int j = 0; j < 4; j++) {
                    sf[i][j] += q4.x*kv4[j].x + q4.y*kv4[j].y
                              + q4.z*kv4[j].z + q4.w*kv4[j].w;
                }
            }
        }

        const int rbase = qt*128 + rg*8;
        const int cbase = kt*64  + cg*4;
        #pragma unroll
        for (int i = 0; i < 8; i++)
            #pragma unroll
            for (int j = 0; j < 4; j++) {
                float v = sf[i][j] * scale;
                if (cbase + j > rbase + i) v = -1e30f;
                sf[i][j] = v;
            }

        #pragma unroll
        for (int i = 0; i < 8; i++) {
            float rm = fmaxf(fmaxf(sf[i][0], sf[i][1]), fmaxf(sf[i][2], sf[i][3]));
            #pragma unroll
            for (int off = 1; off < 16; off <<= 1)
                rm = fmaxf(rm, __shfl_xor_sync(0xffffffffu, rm, off));
            float mn = fmaxf(m_i[i], rm);
            float alpha = expf(m_i[i] - mn);
            m_i[i] = mn;
            float rs = 0.f;
            #pragma unroll
            for (int j = 0; j < 4; j++) {
                float p = expf(sf[i][j] - mn);
                sf[i][j] = p;
                rs += p;
            }
            #pragma unroll
            for (int off = 1; off < 16; off <<= 1)
                rs += __shfl_xor_sync(0xffffffffu, rs, off);
            l_i[i] = l_i[i] * alpha + rs;
            #pragma unroll
            for (int j = 0; j < 8; j++) o[i][j] *= alpha;
            #pragma unroll
            for (int j = 0; j < 4; j++)
                Ps[(rg*8 + i)*68 + cg*4 + j] = sf[i][j];
        }
        __syncthreads();

        for (int c = 0; c < 64; c++) {
            float4 v0 = *reinterpret_cast<const float4*>(&Vs[c*132 + cg*8]);
            float4 v1 = *reinterpret_cast<const float4*>(&Vs[c*132 + cg*8 + 4]);
            #pragma unroll
            for (int i = 0; i < 8; i++) {
                float p = Ps[(rg*8 + i)*68 + c];
                o[i][0] += p * v0.x; o[i][1] += p * v0.y;
                o[i][2] += p * v0.z; o[i][3] += p * v0.w;
                o[i][4] += p * v1.x; o[i][5] += p * v1.y;
                o[i][6] += p * v1.z; o[i][7] += p * v1.w;
            }
        }
        __syncthreads();
    }

    const int b = bh >> 5;
    const int h = bh & 31;
    #pragma unroll
    for (int i = 0; i < 8; i++) {
        float inv = 1.f / l_i[i];
        int s = qt*128 + rg*8 + i;
        float* p = Og + (((size_t)(b * S_ + s) * H_ + h) * HD_ + cg*8);
        *reinterpret_cast<float4*>(p) =
            make_float4(o[i][0]*inv, o[i][1]*inv, o[i][2]*inv, o[i][3]*inv);
        *reinterpret_cast<float4*>(p+4) =
            make_float4(o[i][4]*inv, o[i][5]*inv, o[i][6]*inv, o[i][7]*inv);
    }
}

// ---------------------------------------------------------------------------
// Launch
// ---------------------------------------------------------------------------
extern "C" void kernel_launch(void* const* d_in, const int* in_sizes, int n_in,
                              void* d_out, int out_size)
{
    const float* x  = (const float*)d_in[0];
    const float* fc = (const float*)d_in[1];
    const float* fs = (const float*)d_in[2];
    const float* wq = (const float*)d_in[4];
    const float* wk = (const float*)d_in[5];
    const float* wv = (const float*)d_in[6];
    const float* wo = (const float*)d_in[7];
    float* out = (float*)d_out;

    float *q, *k, *v, *att;
    __nv_bfloat16 *xh, *xl, *bh, *bl;
    cudaGetSymbolAddress((void**)&q,   g_q);
    cudaGetSymbolAddress((void**)&k,   g_k);
    cudaGetSymbolAddress((void**)&v,   g_v);
    cudaGetSymbolAddress((void**)&att, g_att);
    cudaGetSymbolAddress((void**)&xh,  g_xh);
    cudaGetSymbolAddress((void**)&xl,  g_xl);
    cudaGetSymbolAddress((void**)&bh,  g_bh);
    cudaGetSymbolAddress((void**)&bl,  g_bl);

    const size_t attn_smem = (size_t)ATTN_SMEM_FLOATS * sizeof(float);
    cudaFuncSetAttribute(attn_kernel, cudaFuncAttributeMaxDynamicSharedMemorySize,
                         (int)attn_smem);
    cudaFuncSetAttribute(gemm_mma<0>, cudaFuncAttributeMaxDynamicSharedMemorySize, GEMM_SMEM);
    cudaFuncSetAttribute(gemm_mma<1>, cudaFuncAttributeMaxDynamicSharedMemorySize, GEMM_SMEM);
    cudaFuncSetAttribute(gemm_mma<2>, cudaFuncAttributeMaxDynamicSharedMemorySize, GEMM_SMEM);

    const int n4 = D_ * D_ / 4;
    const dim3 sb(256), sg(n4 / 256);
    const dim3 gg(32, 32), gb(256);

    // Split activations + wq, then Q projection (RoPE fused)
    split_kernel<<<sg, sb>>>(x, xh, xl, n4);
    split_kernel<<<sg, sb>>>(wq, bh, bl, n4);
    gemm_mma<2><<<gg, gb, GEMM_SMEM>>>(xh, xl, bh, bl, q, fc, fs);
    // K projection (RoPE fused)
    split_kernel<<<sg, sb>>>(wk, bh, bl, n4);
    gemm_mma<2><<<gg, gb, GEMM_SMEM>>>(xh, xl, bh, bl, k, fc, fs);
    // V projection (scatter only)
    split_kernel<<<sg, sb>>>(wv, bh, bl, n4);
    gemm_mma<1><<<gg, gb, GEMM_SMEM>>>(xh, xl, bh, bl, v, fc, fs);
    // Attention (fp32)
    attn_kernel<<<dim3(16, 64), 256, attn_smem>>>(q, k, v, att);
    // Output projection
    split_kernel<<<sg, sb>>>(att, xh, xl, n4);
    split_kernel<<<sg, sb>>>(wo, bh, bl, n4);
    gemm_mma<0><<<gg, gb, GEMM_SMEM>>>(xh, xl, bh, bl, out, fc, fs);
}

// round 6
// speedup vs baseline: 2.2268x; 1.3593x over previous
#include <cuda_runtime.h>
#include <cuda_bf16.h>
#include <math.h>
#include <stdint.h>

#define B_  2
#define S_  2048
#define D_  4096
#define H_  32
#define HD_ 128
#define NELEM (16777216)        // 4096*4096 == B*H*S*HD

// ---------------------------------------------------------------------------
// Device scratch (bf16 hi/lo everywhere; no fp32 intermediates)
// ---------------------------------------------------------------------------
__device__ __nv_bfloat16 g_xh[NELEM],  g_xl[NELEM];    // x split
__device__ __nv_bfloat16 g_wqh[NELEM], g_wql[NELEM];
__device__ __nv_bfloat16 g_wkh[NELEM], g_wkl[NELEM];
__device__ __nv_bfloat16 g_wvh[NELEM], g_wvl[NELEM];
__device__ __nv_bfloat16 g_woh[NELEM], g_wol[NELEM];
__device__ __nv_bfloat16 g_qh[NELEM],  g_ql[NELEM];    // [B,H,S,HD]
__device__ __nv_bfloat16 g_kh[NELEM],  g_kl[NELEM];
__device__ __nv_bfloat16 g_vh[NELEM],  g_vl[NELEM];
__device__ __nv_bfloat16 g_ath[NELEM], g_atl[NELEM];   // attention out [B*S, D]

// ---------------------------------------------------------------------------
// sm_100-safe PTX helpers
// ---------------------------------------------------------------------------
__device__ __forceinline__ void cp16(uint32_t s, const void* g) {
    asm volatile("cp.async.cg.shared.global [%0], [%1], 16;\n" :: "r"(s), "l"(g) : "memory");
}
__device__ __forceinline__ void cp_commit() {
    asm volatile("cp.async.commit_group;\n" ::: "memory");
}
template<int N> __device__ __forceinline__ void cp_wait() {
    asm volatile("cp.async.wait_group %0;\n" :: "n"(N) : "memory");
}
__device__ __forceinline__ void ldsm4(uint32_t* r, uint32_t addr) {
    asm volatile("ldmatrix.sync.aligned.m8n8.x4.shared.b16 {%0,%1,%2,%3}, [%4];"
        : "=r"(r[0]), "=r"(r[1]), "=r"(r[2]), "=r"(r[3]) : "r"(addr));
}
__device__ __forceinline__ void ldsm4t(uint32_t* r, uint32_t addr) {
    asm volatile("ldmatrix.sync.aligned.m8n8.x4.trans.shared.b16 {%0,%1,%2,%3}, [%4];"
        : "=r"(r[0]), "=r"(r[1]), "=r"(r[2]), "=r"(r[3]) : "r"(addr));
}
__device__ __forceinline__ void mma16816(float* d, const uint32_t* a,
                                         uint32_t b0, uint32_t b1) {
    asm volatile(
        "mma.sync.aligned.m16n8k16.row.col.f32.bf16.bf16.f32 "
        "{%0,%1,%2,%3}, {%4,%5,%6,%7}, {%8,%9}, {%0,%1,%2,%3};"
        : "+f"(d[0]), "+f"(d[1]), "+f"(d[2]), "+f"(d[3])
        : "r"(a[0]), "r"(a[1]), "r"(a[2]), "r"(a[3]), "r"(b0), "r"(b1));
}
__device__ __forceinline__ float ex2(float x) {
    float y; asm("ex2.approx.f32 %0, %1;" : "=f"(y) : "f"(x)); return y;
}
__device__ __forceinline__ uint32_t packbf(float a, float b) {
    __nv_bfloat162 t = __floats2bfloat162_rn(a, b);
    return *reinterpret_cast<uint32_t*>(&t);
}

// ---------------------------------------------------------------------------
// Split fp32 -> (hi bf16, lo bf16)
// ---------------------------------------------------------------------------
__global__ void split_kernel(const float* __restrict__ src,
                             __nv_bfloat16* __restrict__ hi,
                             __nv_bfloat16* __restrict__ lo, int n4)
{
    int i = blockIdx.x * blockDim.x + threadIdx.x;
    if (i >= n4) return;
    float4 v = reinterpret_cast<const float4*>(src)[i];
    __nv_bfloat16 h0 = __float2bfloat16(v.x);
    __nv_bfloat16 h1 = __float2bfloat16(v.y);
    __nv_bfloat16 h2 = __float2bfloat16(v.z);
    __nv_bfloat16 h3 = __float2bfloat16(v.w);
    __nv_bfloat162* hp = reinterpret_cast<__nv_bfloat162*>(hi);
    __nv_bfloat162* lp = reinterpret_cast<__nv_bfloat162*>(lo);
    hp[2*i]   = __halves2bfloat162(h0, h1);
    hp[2*i+1] = __halves2bfloat162(h2, h3);
    lp[2*i]   = __halves2bfloat162(__float2bfloat16(v.x - __bfloat162float(h0)),
                                   __float2bfloat16(v.y - __bfloat162float(h1)));
    lp[2*i+1] = __halves2bfloat162(__float2bfloat16(v.z - __bfloat162float(h2)),
                                   __float2bfloat16(v.w - __bfloat162float(h3)));
}

// ---------------------------------------------------------------------------
// HMMA GEMM (round-4 proven mainloop; bf16 hi/lo epilogues)
// EPI 0: fp32 C[m*4096+n]; EPI 1: split->[B,H,S,HD] hi/lo; EPI 2: +RoPE.
// ---------------------------------------------------------------------------
#define NKT 128
#define ARR_B 10240
#define STAGE_B (4*ARR_B)
#define GEMM_SMEM (3*STAGE_B)

template<int EPI>
__global__ void __launch_bounds__(256, 1)
gemm_mma(const __nv_bfloat16* __restrict__ Ah, const __nv_bfloat16* __restrict__ Al,
         const __nv_bfloat16* __restrict__ Bh, const __nv_bfloat16* __restrict__ Bl,
         float* __restrict__ C,
         __nv_bfloat16* __restrict__ Chi, __nv_bfloat16* __restrict__ Clo,
         const float* __restrict__ cosT, const float* __restrict__ sinT)
{
    extern __shared__ char smem[];
    const uint32_t sb = (uint32_t)__cvta_generic_to_shared(smem);
    const int tid  = threadIdx.x;
    const int wid  = tid >> 5;
    const int lane = tid & 31;
    const int m0 = blockIdx.y * 128;
    const int n0 = blockIdx.x * 128;
    const int wm = (wid >> 2) * 64;
    const int wn = (wid & 3) * 32;

    auto load_stage = [&](int kt, int buf) {
        const uint32_t st = sb + (uint32_t)buf * STAGE_B;
        const int k0 = kt * 32;
        for (int i = tid; i < 512; i += 256) {
            int r = i >> 2, q = i & 3;
            uint32_t so = (uint32_t)(r * 80 + q * 16);
            size_t ga = (size_t)(m0 + r) * D_ + k0 + q * 8;
            size_t gb = (size_t)(n0 + r) * D_ + k0 + q * 8;
            cp16(st + 0*ARR_B + so, Ah + ga);
            cp16(st + 1*ARR_B + so, Al + ga);
            cp16(st + 2*ARR_B + so, Bh + gb);
            cp16(st + 3*ARR_B + so, Bl + gb);
        }
    };

    float acc[4][4][4];
    #pragma unroll
    for (int mt = 0; mt < 4; mt++)
        #pragma unroll
        for (int nt = 0; nt < 4; nt++)
            #pragma unroll
            for (int e = 0; e < 4; e++) acc[mt][nt][e] = 0.f;

    load_stage(0, 0); cp_commit();
    load_stage(1, 1); cp_commit();

    for (int kt = 0; kt < NKT; kt++) {
        __syncthreads();
        if (kt + 2 < NKT) load_stage(kt + 2, (kt + 2) % 3);
        cp_commit();
        cp_wait<2>();
        __syncthreads();

        const uint32_t st = sb + (uint32_t)(kt % 3) * STAGE_B;
        #pragma unroll
        for (int ks = 0; ks < 2; ks++) {
            const int ko = ks * 32 + (lane >> 4) * 16;
            uint32_t ah[4][4], al[4][4], bhq[2][4], blq[2][4];
            const int rA = wm + (lane & 15);
            #pragma unroll
            for (int mt = 0; mt < 4; mt++) {
                uint32_t off = (uint32_t)((rA + mt * 16) * 80 + ko);
                ldsm4(ah[mt], st + 0*ARR_B + off);
                ldsm4(al[mt], st + 1*ARR_B + off);
            }
            const int rB = wn + (lane & 15);
            #pragma unroll
            for (int np = 0; np < 2; np++) {
                uint32_t off = (uint32_t)((rB + np * 16) * 80 + ko);
                ldsm4(bhq[np], st + 2*ARR_B + off);
                ldsm4(blq[np], st + 3*ARR_B + off);
            }
            #pragma unroll
            for (int mt = 0; mt < 4; mt++)
                #pragma unroll
                for (int nt = 0; nt < 4; nt++) {
                    const int np = nt >> 1, sel = nt & 1;
                    mma16816(acc[mt][nt], ah[mt], bhq[np][sel], bhq[np][sel + 2]);
                    mma16816(acc[mt][nt], ah[mt], blq[np][sel], blq[np][sel + 2]);
                    mma16816(acc[mt][nt], al[mt], bhq[np][sel], bhq[np][sel + 2]);
                }
        }
    }

    #pragma unroll
    for (int mt = 0; mt < 4; mt++) {
        #pragma unroll
        for (int nt = 0; nt < 4; nt++) {
            const int mrow = m0 + wm + mt * 16 + (lane >> 2);
            const int col  = wn + nt * 8 + 2 * (lane & 3);
            #pragma unroll
            for (int hrow = 0; hrow < 2; hrow++) {
                const int m = mrow + hrow * 8;
                float e = acc[mt][nt][2*hrow], o = acc[mt][nt][2*hrow + 1];
                if (EPI == 0) {
                    float* p = &C[(size_t)m * D_ + n0 + col];
                    p[0] = e; p[1] = o;
                } else {
                    const int b = m >> 11, s = m & (S_ - 1);
                    if (EPI == 2) {
                        float cc = cosT[s * 64 + (col >> 1)];
                        float ss = sinT[s * 64 + (col >> 1)];
                        float t0 = e * cc - o * ss;
                        o = e * ss + o * cc;
                        e = t0;
                    }
                    __nv_bfloat16 he = __float2bfloat16(e);
                    __nv_bfloat16 ho = __float2bfloat16(o);
                    size_t idx = (((size_t)(b * H_ + blockIdx.x) * S_ + s) * HD_ + col);
                    *reinterpret_cast<__nv_bfloat162*>(&Chi[idx]) = __halves2bfloat162(he, ho);
                    *reinterpret_cast<__nv_bfloat162*>(&Clo[idx]) =
                        __halves2bfloat162(__float2bfloat16(e - __bfloat162float(he)),
                                           __float2bfloat16(o - __bfloat162float(ho)));
                }
            }
        }
    }
}

// ---------------------------------------------------------------------------
// Tensor-core flash attention. Block = (qtile 128 rows, bh). 8 warps; each
// warp owns 16 q-rows x full kv width. QK^T: 3-pass bf16 hi/lo. Softmax
// fp32 (ex2). PV: 3-pass (P split hi/lo, V split hi/lo). Output written as
// bf16 hi/lo att [B*S, 4096].
// ---------------------------------------------------------------------------
#define ATT_SMEM 208896
#define ATQH 0
#define ATQL 34816
#define ATKH 69632
#define ATKL 104448
#define ATVH 139264
#define ATVL 174080
#define KVBUF 17408
#define L2E 1.4426950408889634f

__global__ void __launch_bounds__(256, 1)
attn_mma(const __nv_bfloat16* __restrict__ Qh, const __nv_bfloat16* __restrict__ Ql,
         const __nv_bfloat16* __restrict__ Kh, const __nv_bfloat16* __restrict__ Kl,
         const __nv_bfloat16* __restrict__ Vh, const __nv_bfloat16* __restrict__ Vl,
         __nv_bfloat16* __restrict__ Oh, __nv_bfloat16* __restrict__ Ol)
{
    extern __shared__ char smc[];
    const uint32_t sb = (uint32_t)__cvta_generic_to_shared(smc);
    const int tid = threadIdx.x, wid = tid >> 5, lane = tid & 31;
    const int bh = blockIdx.x;
    const int qt = 15 - blockIdx.y;         // heavy tiles first
    const size_t base = (size_t)bh * S_ * HD_;
    const float scale = 0.08838834764831843f;

    // Load Q tile (128 x 128 bf16, hi+lo)
    for (int i = tid; i < 2048; i += 256) {
        int r = i >> 4, j = i & 15;
        uint32_t d = (uint32_t)(r * 272 + j * 16);
        size_t g = base + (size_t)(qt * 128 + r) * HD_ + j * 8;
        cp16(sb + ATQH + d, Qh + g);
        cp16(sb + ATQL + d, Ql + g);
    }

    auto loadkv = [&](int kt, int buf) {
        const uint32_t bo = (uint32_t)buf * KVBUF;
        for (int i = tid; i < 1024; i += 256) {
            int r = i >> 4, j = i & 15;
            uint32_t d = (uint32_t)(r * 272 + j * 16);
            size_t g = base + (size_t)(kt * 64 + r) * HD_ + j * 8;
            cp16(sb + ATKH + bo + d, Kh + g);
            cp16(sb + ATKL + bo + d, Kl + g);
            cp16(sb + ATVH + bo + d, Vh + g);
            cp16(sb + ATVL + bo + d, Vl + g);
        }
    };

    loadkv(0, 0);
    cp_commit();

    float o[16][4];
    #pragma unroll
    for (int nt = 0; nt < 16; nt++)
        #pragma unroll
        for (int e = 0; e < 4; e++) o[nt][e] = 0.f;
    float m_i[2] = {-1e30f, -1e30f}, l_i[2] = {0.f, 0.f};

    const int nkv = 2 * qt + 2;
    const int row0 = qt * 128 + wid * 16 + (lane >> 2);   // global q row (half 0)

    for (int kt = 0; kt < nkv; kt++) {
        cp_wait<0>();
        __syncthreads();
        if (kt + 1 < nkv) { loadkv(kt + 1, (kt + 1) & 1); cp_commit(); }

        const uint32_t khb = sb + ATKH + (uint32_t)(kt & 1) * KVBUF;
        const uint32_t klb = sb + ATKL + (uint32_t)(kt & 1) * KVBUF;
        const uint32_t vhb = sb + ATVH + (uint32_t)(kt & 1) * KVBUF;
        const uint32_t vlb = sb + ATVL + (uint32_t)(kt & 1) * KVBUF;

        // ---- S = Q K^T (3-pass) : warp tile 16 x 64 ----
        float sc[8][4];
        #pragma unroll
        for (int nt = 0; nt < 8; nt++)
            #pragma unroll
            for (int e = 0; e < 4; e++) sc[nt][e] = 0.f;

        #pragma unroll
        for (int ks = 0; ks < 8; ks++) {
            const uint32_t ko = (uint32_t)(ks * 32 + (lane >> 4) * 16);
            uint32_t aqh[4], aql[4], bkh[4][4], bkl[4][4];
            uint32_t aoff = (uint32_t)((wid * 16 + (lane & 15)) * 272) + ko;
            ldsm4(aqh, sb + ATQH + aoff);
            ldsm4(aql, sb + ATQL + aoff);
            #pragma unroll
            for (int np = 0; np < 4; np++) {
                uint32_t boff = (uint32_t)((np * 16 + (lane & 15)) * 272) + ko;
                ldsm4(bkh[np], khb + boff);
                ldsm4(bkl[np], klb + boff);
            }
            #pragma unroll
            for (int nt = 0; nt < 8; nt++) {
                const int np = nt >> 1, sel = nt & 1;
                mma16816(sc[nt], aqh, bkh[np][sel], bkh[np][sel + 2]);
                mma16816(sc[nt], aqh, bkl[np][sel], bkl[np][sel + 2]);
                mma16816(sc[nt], aql, bkh[np][sel], bkh[np][sel + 2]);
            }
        }

        // ---- scale + causal mask ----
        #pragma unroll
        for (int nt = 0; nt < 8; nt++)
            #pragma unroll
            for (int e = 0; e < 4; e++) sc[nt][e] *= scale;
        if (kt >= 2 * qt) {
            #pragma unroll
            for (int nt = 0; nt < 8; nt++)
                #pragma unroll
                for (int e = 0; e < 4; e++) {
                    int col = kt * 64 + nt * 8 + 2 * (lane & 3) + (e & 1);
                    int row = row0 + (e >> 1) * 8;
                    if (col > row) sc[nt][e] = -1e30f;
                }
        }

        // ---- online softmax ----
        float rmax0 = -1e30f, rmax1 = -1e30f;
        #pragma unroll
        for (int nt = 0; nt < 8; nt++) {
            rmax0 = fmaxf(rmax0, fmaxf(sc[nt][0], sc[nt][1]));
            rmax1 = fmaxf(rmax1, fmaxf(sc[nt][2], sc[nt][3]));
        }
        #pragma unroll
        for (int off = 1; off < 4; off <<= 1) {
            rmax0 = fmaxf(rmax0, __shfl_xor_sync(0xffffffffu, rmax0, off));
            rmax1 = fmaxf(rmax1, __shfl_xor_sync(0xffffffffu, rmax1, off));
        }
        float mn0 = fmaxf(m_i[0], rmax0);
        float mn1 = fmaxf(m_i[1], rmax1);
        float al0 = ex2((m_i[0] - mn0) * L2E);
        float al1 = ex2((m_i[1] - mn1) * L2E);
        m_i[0] = mn0; m_i[1] = mn1;

        uint32_t ph01[8], ph23[8], pl01[8], pl23[8];
        float rs0 = 0.f, rs1 = 0.f;
        #pragma unroll
        for (int nt = 0; nt < 8; nt++) {
            float p0 = ex2((sc[nt][0] - mn0) * L2E);
            float p1 = ex2((sc[nt][1] - mn0) * L2E);
            float p2 = ex2((sc[nt][2] - mn1) * L2E);
            float p3 = ex2((sc[nt][3] - mn1) * L2E);
            rs0 += p0 + p1; rs1 += p2 + p3;
            __nv_bfloat16 b0 = __float2bfloat16(p0), b1 = __float2bfloat16(p1);
            __nv_bfloat16 b2 = __float2bfloat16(p2), b3 = __float2bfloat16(p3);
            __nv_bfloat162 h01 = __halves2bfloat162(b0, b1);
            __nv_bfloat162 h23 = __halves2bfloat162(b2, b3);
            ph01[nt] = *reinterpret_cast<uint32_t*>(&h01);
            ph23[nt] = *reinterpret_cast<uint32_t*>(&h23);
            pl01[nt] = packbf(p0 - __bfloat162float(b0), p1 - __bfloat162float(b1));
            pl23[nt] = packbf(p2 - __bfloat162float(b2), p3 - __bfloat162float(b3));
        }
        #pragma unroll
        for (int off = 1; off < 4; off <<= 1) {
            rs0 += __shfl_xor_sync(0xffffffffu, rs0, off);
            rs1 += __shfl_xor_sync(0xffffffffu, rs1, off);
        }
        l_i[0] = l_i[0] * al0 + rs0;
        l_i[1] = l_i[1] * al1 + rs1;
        #pragma unroll
        for (int nt = 0; nt < 16; nt++) {
            o[nt][0] *= al0; o[nt][1] *= al0;
            o[nt][2] *= al1; o[nt][3] *= al1;
        }

        // ---- O += P V (3-pass) : warp tile 16 x 128 ----
        #pragma unroll
        for (int kki = 0; kki < 4; kki++) {
            uint32_t aPh[4] = {ph01[2*kki], ph23[2*kki], ph01[2*kki+1], ph23[2*kki+1]};
            uint32_t aPl[4] = {pl01[2*kki], pl23[2*kki], pl01[2*kki+1], pl23[2*kki+1]};
            const int g = lane >> 3, li = lane & 7;
            #pragma unroll
            for (int dj = 0; dj < 8; dj++) {
                uint32_t vh4[4], vl4[4];
                uint32_t voff = (uint32_t)((kki * 16 + (g & 1) * 8 + li) * 272
                                           + (dj * 16 + (g >> 1) * 8) * 2);
                ldsm4t(vh4, vhb + voff);
                ldsm4t(vl4, vlb + voff);
                #pragma unroll
                for (int sel = 0; sel < 2; sel++) {
                    const int nt = dj * 2 + sel;
                    mma16816(o[nt], aPh, vh4[2*sel], vh4[2*sel+1]);
                    mma16816(o[nt], aPh, vl4[2*sel], vl4[2*sel+1]);
                    mma16816(o[nt], aPl, vh4[2*sel], vh4[2*sel+1]);
                }
            }
        }
    }

    // ---- epilogue: normalize, split bf16 hi/lo, scatter to att [B*S, 4096]
    const float inv0 = 1.f / l_i[0];
    const float inv1 = 1.f / l_i[1];
    const int b = bh >> 5, head = bh & 31;
    #pragma unroll
    for (int nt = 0; nt < 16; nt++) {
        const int col = head * 128 + nt * 8 + 2 * (lane & 3);
        #pragma unroll
        for (int hrow = 0; hrow < 2; hrow++) {
            float e = o[nt][2*hrow]     * (hrow ? inv1 : inv0);
            float od = o[nt][2*hrow + 1] * (hrow ? inv1 : inv0);
            int m = b * S_ + row0 + hrow * 8;
            __nv_bfloat16 he = __float2bfloat16(e);
            __nv_bfloat16 ho = __float2bfloat16(od);
            size_t idx = (size_t)m * D_ + col;
            *reinterpret_cast<__nv_bfloat162*>(&Oh[idx]) = __halves2bfloat162(he, ho);
            *reinterpret_cast<__nv_bfloat162*>(&Ol[idx]) =
                __halves2bfloat162(__float2bfloat16(e - __bfloat162float(he)),
                                   __float2bfloat16(od - __bfloat162float(ho)));
        }
    }
}

// ---------------------------------------------------------------------------
// Launch (splits hoisted so ncu -s 5 lands on the first GEMM)
// ---------------------------------------------------------------------------
extern "C" void kernel_launch(void* const* d_in, const int* in_sizes, int n_in,
                              void* d_out, int out_size)
{
    const float* x  = (const float*)d_in[0];
    const float* fc = (const float*)d_in[1];
    const float* fs = (const float*)d_in[2];
    const float* wq = (const float*)d_in[4];
    const float* wk = (const float*)d_in[5];
    const float* wv = (const float*)d_in[6];
    const float* wo = (const float*)d_in[7];
    float* out = (float*)d_out;

    __nv_bfloat16 *xh, *xl, *wqh, *wql, *wkh, *wkl, *wvh, *wvl, *woh, *wol;
    __nv_bfloat16 *qh, *ql, *kh, *kl, *vh, *vl, *ath, *atl;
    cudaGetSymbolAddress((void**)&xh,  g_xh);  cudaGetSymbolAddress((void**)&xl,  g_xl);
    cudaGetSymbolAddress((void**)&wqh, g_wqh); cudaGetSymbolAddress((void**)&wql, g_wql);
    cudaGetSymbolAddress((void**)&wkh, g_wkh); cudaGetSymbolAddress((void**)&wkl, g_wkl);
    cudaGetSymbolAddress((void**)&wvh, g_wvh); cudaGetSymbolAddress((void**)&wvl, g_wvl);
    cudaGetSymbolAddress((void**)&woh, g_woh); cudaGetSymbolAddress((void**)&wol, g_wol);
    cudaGetSymbolAddress((void**)&qh,  g_qh);  cudaGetSymbolAddress((void**)&ql,  g_ql);
    cudaGetSymbolAddress((void**)&kh,  g_kh);  cudaGetSymbolAddress((void**)&kl,  g_kl);
    cudaGetSymbolAddress((void**)&vh,  g_vh);  cudaGetSymbolAddress((void**)&vl,  g_vl);
    cudaGetSymbolAddress((void**)&ath, g_ath); cudaGetSymbolAddress((void**)&atl, g_atl);

    cudaFuncSetAttribute(gemm_mma<0>, cudaFuncAttributeMaxDynamicSharedMemorySize, GEMM_SMEM);
    cudaFuncSetAttribute(gemm_mma<1>, cudaFuncAttributeMaxDynamicSharedMemorySize, GEMM_SMEM);
    cudaFuncSetAttribute(gemm_mma<2>, cudaFuncAttributeMaxDynamicSharedMemorySize, GEMM_SMEM);
    cudaFuncSetAttribute(attn_mma,    cudaFuncAttributeMaxDynamicSharedMemorySize, ATT_SMEM);

    const int n4 = D_ * D_ / 4;
    const dim3 sbk(256), sgd(n4 / 256);
    const dim3 gg(32, 32), gb(256);

    // 0-4: all splits first
    split_kernel<<<sgd, sbk>>>(x,  xh,  xl,  n4);
    split_kernel<<<sgd, sbk>>>(wq, wqh, wql, n4);
    split_kernel<<<sgd, sbk>>>(wk, wkh, wkl, n4);
    split_kernel<<<sgd, sbk>>>(wv, wvh, wvl, n4);
    split_kernel<<<sgd, sbk>>>(wo, woh, wol, n4);
    // 5-7: projections (RoPE fused into Q/K; all write bf16 hi/lo)
    gemm_mma<2><<<gg, gb, GEMM_SMEM>>>(xh, xl, wqh, wql, nullptr, qh, ql, fc, fs);
    gemm_mma<2><<<gg, gb, GEMM_SMEM>>>(xh, xl, wkh, wkl, nullptr, kh, kl, fc, fs);
    gemm_mma<1><<<gg, gb, GEMM_SMEM>>>(xh, xl, wvh, wvl, nullptr, vh, vl, fc, fs);
    // 8: tensor-core attention
    attn_mma<<<dim3(64, 16), 256, ATT_SMEM>>>(qh, ql, kh, kl, vh, vl, ath, atl);
    // 9: output projection -> d_out (fp32)
    gemm_mma<0><<<gg, gb, GEMM_SMEM>>>(ath, atl, woh, wol, out, nullptr, nullptr, fc, fs);
}

// round 7
// speedup vs baseline: 2.8467x; 1.2784x over previous
#include <cuda_runtime.h>
#include <cuda_bf16.h>
#include <math.h>
#include <stdint.h>

#define B_  2
#define S_  2048
#define D_  4096
#define H_  32
#define HD_ 128

// Blocked GEMM-operand layout: [kt=128][row=4096][40 elems (80B, 32 data + 8 pad)]
#define BLK_ELEMS 20971520            // 128*4096*40
#define BLK_KT_ELEMS 163840           // 4096*40
#define BLK_KT_BYTES 327680
// Padded QKV layout: [B,H,S,136 elems (272B, 128 data + 8 pad)]
#define QKV_ELEMS 17825792            // 2*32*2048*136

__device__ __nv_bfloat16 g_xh[BLK_ELEMS],  g_xl[BLK_ELEMS];
__device__ __nv_bfloat16 g_wqh[BLK_ELEMS], g_wql[BLK_ELEMS];
__device__ __nv_bfloat16 g_wkh[BLK_ELEMS], g_wkl[BLK_ELEMS];
__device__ __nv_bfloat16 g_wvh[BLK_ELEMS], g_wvl[BLK_ELEMS];
__device__ __nv_bfloat16 g_woh[BLK_ELEMS], g_wol[BLK_ELEMS];
__device__ __nv_bfloat16 g_ath[BLK_ELEMS], g_atl[BLK_ELEMS];
__device__ __nv_bfloat16 g_qh[QKV_ELEMS],  g_ql[QKV_ELEMS];
__device__ __nv_bfloat16 g_kh[QKV_ELEMS],  g_kl[QKV_ELEMS];
__device__ __nv_bfloat16 g_vh[QKV_ELEMS],  g_vl[QKV_ELEMS];

// ---------------------------------------------------------------------------
// sm_100-safe PTX helpers (all proven to compile on this toolchain)
// ---------------------------------------------------------------------------
#define MBARRIER_INIT(addr, count) \
    asm volatile("mbarrier.init.shared.b64 [%0], %1;" :: "r"((uint32_t)(addr)), "r"((uint32_t)(count)) : "memory")
#define MBARRIER_EXPECT_TX(addr, tx) \
    asm volatile("mbarrier.arrive.expect_tx.shared.b64 _, [%0], %1;" :: "r"((uint32_t)(addr)), "r"((uint32_t)(tx)) : "memory")
#define FENCE_PROXY_ASYNC() asm volatile("fence.proxy.async.shared::cta;" ::: "memory")

#define MBARRIER_WAIT_PARITY(mbar_smem_addr, phase_parity) do { \
    uint32_t _mbar = (uint32_t)(mbar_smem_addr); \
    uint32_t _parity = (uint32_t)(phase_parity); \
    uint32_t _done; \
    asm volatile( \
        "{\n\t.reg .pred p;\n\t" \
        "mbarrier.try_wait.parity.acquire.cta.shared::cta.b64 p, [%1], %2;\n\t" \
        "selp.b32 %0, 1, 0, p;\n\t}" \
        : "=r"(_done) : "r"(_mbar), "r"(_parity) : "memory"); \
    if (!_done) { \
        asm volatile( \
            "{\n\t.reg .pred P1;\n\t" \
            "WAIT_LOOP_%=:\n\t" \
            "mbarrier.try_wait.parity.acquire.cta.shared::cta.b64 P1, [%0], %1, 0x989680;\n\t" \
            "@P1 bra.uni WAIT_DONE_%=;\n\t" \
            "bra.uni WAIT_LOOP_%=;\n\t" \
            "WAIT_DONE_%=:\n\t}" \
            :: "r"(_mbar), "r"(_parity) : "memory"); \
    } \
} while(0)

__device__ __forceinline__ void bulkld(uint32_t dst, const void* src,
                                       uint32_t bytes, uint32_t mbar) {
    asm volatile(
        "cp.async.bulk.shared::cluster.global.mbarrier::complete_tx::bytes [%0], [%1], %2, [%3];"
        :: "r"(dst), "l"(src), "r"(bytes), "r"(mbar) : "memory");
}
__device__ __forceinline__ void ldsm4(uint32_t* r, uint32_t addr) {
    asm volatile("ldmatrix.sync.aligned.m8n8.x4.shared.b16 {%0,%1,%2,%3}, [%4];"
        : "=r"(r[0]), "=r"(r[1]), "=r"(r[2]), "=r"(r[3]) : "r"(addr));
}
__device__ __forceinline__ void ldsm4t(uint32_t* r, uint32_t addr) {
    asm volatile("ldmatrix.sync.aligned.m8n8.x4.trans.shared.b16 {%0,%1,%2,%3}, [%4];"
        : "=r"(r[0]), "=r"(r[1]), "=r"(r[2]), "=r"(r[3]) : "r"(addr));
}
__device__ __forceinline__ void mma16816(float* d, const uint32_t* a,
                                         uint32_t b0, uint32_t b1) {
    asm volatile(
        "mma.sync.aligned.m16n8k16.row.col.f32.bf16.bf16.f32 "
        "{%0,%1,%2,%3}, {%4,%5,%6,%7}, {%8,%9}, {%0,%1,%2,%3};"
        : "+f"(d[0]), "+f"(d[1]), "+f"(d[2]), "+f"(d[3])
        : "r"(a[0]), "r"(a[1]), "r"(a[2]), "r"(a[3]), "r"(b0), "r"(b1));
}
__device__ __forceinline__ float ex2(float x) {
    float y; asm("ex2.approx.f32 %0, %1;" : "=f"(y) : "f"(x)); return y;
}
__device__ __forceinline__ uint32_t packbf(float a, float b) {
    __nv_bfloat162 t = __floats2bfloat162_rn(a, b);
    return *reinterpret_cast<uint32_t*>(&t);
}

// ---------------------------------------------------------------------------
// Split fp32 [R,4096] -> bf16 hi/lo in blocked layout [kt][row][40]
// ---------------------------------------------------------------------------
__global__ void split_blocked(const float* __restrict__ src,
                              __nv_bfloat16* __restrict__ hi,
                              __nv_bfloat16* __restrict__ lo, int n4)
{
    int i = blockIdx.x * blockDim.x + threadIdx.x;
    if (i >= n4) return;
    int lin = i * 4;
    int m = lin >> 12;
    int k = lin & 4095;
    size_t base = (size_t)(k >> 5) * BLK_KT_ELEMS + (size_t)m * 40 + (k & 31);
    float4 v = reinterpret_cast<const float4*>(src)[i];
    __nv_bfloat16 h0 = __float2bfloat16(v.x);
    __nv_bfloat16 h1 = __float2bfloat16(v.y);
    __nv_bfloat16 h2 = __float2bfloat16(v.z);
    __nv_bfloat16 h3 = __float2bfloat16(v.w);
    __nv_bfloat162* hp = reinterpret_cast<__nv_bfloat162*>(hi + base);
    __nv_bfloat162* lp = reinterpret_cast<__nv_bfloat162*>(lo + base);
    hp[0] = __halves2bfloat162(h0, h1);
    hp[1] = __halves2bfloat162(h2, h3);
    lp[0] = __halves2bfloat162(__float2bfloat16(v.x - __bfloat162float(h0)),
                               __float2bfloat16(v.y - __bfloat162float(h1)));
    lp[1] = __halves2bfloat162(__float2bfloat16(v.z - __bfloat162float(h2)),
                               __float2bfloat16(v.w - __bfloat162float(h3)));
}

// ---------------------------------------------------------------------------
// HMMA GEMM, bulk-fed: C = A B^T (4096^3), bf16x3 hi/lo, tile 128x128, BK=32,
// 3-stage cp.async.bulk + mbarrier pipeline. Compute identical to round 6.
// EPI 0: fp32 C; EPI 1: QKV padded hi/lo; EPI 2: +RoPE.
// ---------------------------------------------------------------------------
#define NKT 128
#define ARR_B 10240
#define STAGE_B 40960
#define GEMM_SMEM (64 + 3*STAGE_B)

template<int EPI>
__global__ void __launch_bounds__(256, 1)
gemm_mma(const __nv_bfloat16* __restrict__ Ah, const __nv_bfloat16* __restrict__ Al,
         const __nv_bfloat16* __restrict__ Bh, const __nv_bfloat16* __restrict__ Bl,
         float* __restrict__ C,
         __nv_bfloat16* __restrict__ Chi, __nv_bfloat16* __restrict__ Clo,
         const float* __restrict__ cosT, const float* __restrict__ sinT)
{
    extern __shared__ char smem[];
    const uint32_t sb = (uint32_t)__cvta_generic_to_shared(smem);
    const int tid  = threadIdx.x;
    const int wid  = tid >> 5;
    const int lane = tid & 31;
    const int m0 = blockIdx.y * 128;
    const int n0 = blockIdx.x * 128;
    const int wm = (wid >> 2) * 64;
    const int wn = (wid & 3) * 32;

    if (tid == 0) {
        MBARRIER_INIT(sb + 0,  1);
        MBARRIER_INIT(sb + 8,  1);
        MBARRIER_INIT(sb + 16, 1);
        FENCE_PROXY_ASYNC();
    }
    __syncthreads();

    auto issue = [&](int kt, int buf) {
        if (tid == 0) {
            uint32_t mb = sb + (uint32_t)buf * 8;
            MBARRIER_EXPECT_TX(mb, STAGE_B);
            const uint32_t st = sb + 64 + (uint32_t)buf * STAGE_B;
            size_t ao = (size_t)kt * BLK_KT_BYTES + (size_t)m0 * 80;
            size_t bo = (size_t)kt * BLK_KT_BYTES + (size_t)n0 * 80;
            bulkld(st + 0*ARR_B, (const char*)Ah + ao, ARR_B, mb);
            bulkld(st + 1*ARR_B, (const char*)Al + ao, ARR_B, mb);
            bulkld(st + 2*ARR_B, (const char*)Bh + bo, ARR_B, mb);
            bulkld(st + 3*ARR_B, (const char*)Bl + bo, ARR_B, mb);
        }
    };

    float acc[4][4][4];
    #pragma unroll
    for (int mt = 0; mt < 4; mt++)
        #pragma unroll
        for (int nt = 0; nt < 4; nt++)
            #pragma unroll
            for (int e = 0; e < 4; e++) acc[mt][nt][e] = 0.f;

    issue(0, 0); issue(1, 1); issue(2, 2);

    for (int kt = 0; kt < NKT; kt++) {
        const int buf = kt % 3;
        MBARRIER_WAIT_PARITY(sb + buf * 8, (kt / 3) & 1);

        const uint32_t st = sb + 64 + (uint32_t)buf * STAGE_B;
        #pragma unroll
        for (int ks = 0; ks < 2; ks++) {
            const int ko = ks * 32 + (lane >> 4) * 16;
            uint32_t ah[4][4], al[4][4], bhq[2][4], blq[2][4];
            const int rA = wm + (lane & 15);
            #pragma unroll
            for (int mt = 0; mt < 4; mt++) {
                uint32_t off = (uint32_t)((rA + mt * 16) * 80 + ko);
                ldsm4(ah[mt], st + 0*ARR_B + off);
                ldsm4(al[mt], st + 1*ARR_B + off);
            }
            const int rB = wn + (lane & 15);
            #pragma unroll
            for (int np = 0; np < 2; np++) {
                uint32_t off = (uint32_t)((rB + np * 16) * 80 + ko);
                ldsm4(bhq[np], st + 2*ARR_B + off);
                ldsm4(blq[np], st + 3*ARR_B + off);
            }
            #pragma unroll
            for (int mt = 0; mt < 4; mt++)
                #pragma unroll
                for (int nt = 0; nt < 4; nt++) {
                    const int np = nt >> 1, sel = nt & 1;
                    mma16816(acc[mt][nt], ah[mt], bhq[np][sel], bhq[np][sel + 2]);
                    mma16816(acc[mt][nt], ah[mt], blq[np][sel], blq[np][sel + 2]);
                    mma16816(acc[mt][nt], al[mt], bhq[np][sel], bhq[np][sel + 2]);
                }
        }
        __syncthreads();
        if (kt + 3 < NKT) issue(kt + 3, buf);
    }

    #pragma unroll
    for (int mt = 0; mt < 4; mt++) {
        #pragma unroll
        for (int nt = 0; nt < 4; nt++) {
            const int mrow = m0 + wm + mt * 16 + (lane >> 2);
            const int col  = wn + nt * 8 + 2 * (lane & 3);
            #pragma unroll
            for (int hrow = 0; hrow < 2; hrow++) {
                const int m = mrow + hrow * 8;
                float e = acc[mt][nt][2*hrow], o = acc[mt][nt][2*hrow + 1];
                if (EPI == 0) {
                    float* p = &C[(size_t)m * D_ + n0 + col];
                    p[0] = e; p[1] = o;
                } else {
                    const int b = m >> 11, s = m & (S_ - 1);
                    if (EPI == 2) {
                        float cc = cosT[s * 64 + (col >> 1)];
                        float ss = sinT[s * 64 + (col >> 1)];
                        float t0 = e * cc - o * ss;
                        o = e * ss + o * cc;
                        e = t0;
                    }
                    __nv_bfloat16 he = __float2bfloat16(e);
                    __nv_bfloat16 ho = __float2bfloat16(o);
                    size_t idx = ((size_t)(b * H_ + blockIdx.x) * S_ + s) * 136 + col;
                    *reinterpret_cast<__nv_bfloat162*>(&Chi[idx]) = __halves2bfloat162(he, ho);
                    *reinterpret_cast<__nv_bfloat162*>(&Clo[idx]) =
                        __halves2bfloat162(__float2bfloat16(e - __bfloat162float(he)),
                                           __float2bfloat16(o - __bfloat162float(ho)));
                }
            }
        }
    }
}

// ---------------------------------------------------------------------------
// Tensor-core flash attention, bulk-fed. Compute identical to round 6.
// Inputs: padded QKV [B,H,S,272B]. Output: blocked att hi/lo for final GEMM.
// smem: mbars 64B; QH@64, QL@34880; KH@69696, KL@104512, VH@139328,
// VL@174144 (each 2 bufs x 17408). Total 208960.
// ---------------------------------------------------------------------------
#define ATT_SMEM 208960
#define AQH 64
#define AQL 34880
#define AKH 69696
#define AKL 104512
#define AVH 139328
#define AVL 174144
#define KVB 17408
#define L2E 1.4426950408889634f

__global__ void __launch_bounds__(256, 1)
attn_mma(const __nv_bfloat16* __restrict__ Qh, const __nv_bfloat16* __restrict__ Ql,
         const __nv_bfloat16* __restrict__ Kh, const __nv_bfloat16* __restrict__ Kl,
         const __nv_bfloat16* __restrict__ Vh, const __nv_bfloat16* __restrict__ Vl,
         __nv_bfloat16* __restrict__ Oh, __nv_bfloat16* __restrict__ Ol)
{
    extern __shared__ char smc[];
    const uint32_t sb = (uint32_t)__cvta_generic_to_shared(smc);
    const int tid = threadIdx.x, wid = tid >> 5, lane = tid & 31;
    const int bh = blockIdx.x;
    const int qt = 15 - blockIdx.y;
    const float scale = 0.08838834764831843f;
    const int nkv = 2 * qt + 2;

    if (tid == 0) {
        MBARRIER_INIT(sb + 0,  1);   // Q
        MBARRIER_INIT(sb + 8,  1);   // KV buf 0
        MBARRIER_INIT(sb + 16, 1);   // KV buf 1
        FENCE_PROXY_ASYNC();
    }
    __syncthreads();

    if (tid == 0) {
        size_t qo = ((size_t)bh * S_ + (size_t)qt * 128) * 272;
        MBARRIER_EXPECT_TX(sb + 0, 69632);
        bulkld(sb + AQH, (const char*)Qh + qo, 34816, sb + 0);
        bulkld(sb + AQL, (const char*)Ql + qo, 34816, sb + 0);
    }
    auto issuekv = [&](int kt, int buf) {
        if (tid == 0) {
            uint32_t mb = sb + 8 + (uint32_t)buf * 8;
            size_t o = ((size_t)bh * S_ + (size_t)kt * 64) * 272;
            MBARRIER_EXPECT_TX(mb, 4 * KVB);
            uint32_t bo = (uint32_t)buf * KVB;
            bulkld(sb + AKH + bo, (const char*)Kh + o, KVB, mb);
            bulkld(sb + AKL + bo, (const char*)Kl + o, KVB, mb);
            bulkld(sb + AVH + bo, (const char*)Vh + o, KVB, mb);
            bulkld(sb + AVL + bo, (const char*)Vl + o, KVB, mb);
        }
    };
    issuekv(0, 0);
    issuekv(1, 1);

    float o[16][4];
    #pragma unroll
    for (int nt = 0; nt < 16; nt++)
        #pragma unroll
        for (int e = 0; e < 4; e++) o[nt][e] = 0.f;
    float m_i[2] = {-1e30f, -1e30f}, l_i[2] = {0.f, 0.f};
    const int row0 = qt * 128 + wid * 16 + (lane >> 2);

    MBARRIER_WAIT_PARITY(sb + 0, 0);   // Q resident

    for (int kt = 0; kt < nkv; kt++) {
        const int buf = kt & 1;
        MBARRIER_WAIT_PARITY(sb + 8 + buf * 8, (kt >> 1) & 1);

        const uint32_t khb = sb + AKH + (uint32_t)buf * KVB;
        const uint32_t klb = sb + AKL + (uint32_t)buf * KVB;
        const uint32_t vhb = sb + AVH + (uint32_t)buf * KVB;
        const uint32_t vlb = sb + AVL + (uint32_t)buf * KVB;

        // ---- S = Q K^T (3-pass) ----
        float sc[8][4];
        #pragma unroll
        for (int nt = 0; nt < 8; nt++)
            #pragma unroll
            for (int e = 0; e < 4; e++) sc[nt][e] = 0.f;

        #pragma unroll
        for (int ks = 0; ks < 8; ks++) {
            const uint32_t ko = (uint32_t)(ks * 32 + (lane >> 4) * 16);
            uint32_t aqh[4], aql[4], bkh[4][4], bkl[4][4];
            uint32_t aoff = (uint32_t)((wid * 16 + (lane & 15)) * 272) + ko;
            ldsm4(aqh, sb + AQH + aoff);
            ldsm4(aql, sb + AQL + aoff);
            #pragma unroll
            for (int np = 0; np < 4; np++) {
                uint32_t boff = (uint32_t)((np * 16 + (lane & 15)) * 272) + ko;
                ldsm4(bkh[np], khb + boff);
                ldsm4(bkl[np], klb + boff);
            }
            #pragma unroll
            for (int nt = 0; nt < 8; nt++) {
                const int np = nt >> 1, sel = nt & 1;
                mma16816(sc[nt], aqh, bkh[np][sel], bkh[np][sel + 2]);
                mma16816(sc[nt], aqh, bkl[np][sel], bkl[np][sel + 2]);
                mma16816(sc[nt], aql, bkh[np][sel], bkh[np][sel + 2]);
            }
        }

        // ---- scale + causal mask ----
        #pragma unroll
        for (int nt = 0; nt < 8; nt++)
            #pragma unroll
            for (int e = 0; e < 4; e++) sc[nt][e] *= scale;
        if (kt >= 2 * qt) {
            #pragma unroll
            for (int nt = 0; nt < 8; nt++)
                #pragma unroll
                for (int e = 0; e < 4; e++) {
                    int col = kt * 64 + nt * 8 + 2 * (lane & 3) + (e & 1);
                    int row = row0 + (e >> 1) * 8;
                    if (col > row) sc[nt][e] = -1e30f;
                }
        }

        // ---- online softmax ----
        float rmax0 = -1e30f, rmax1 = -1e30f;
        #pragma unroll
        for (int nt = 0; nt < 8; nt++) {
            rmax0 = fmaxf(rmax0, fmaxf(sc[nt][0], sc[nt][1]));
            rmax1 = fmaxf(rmax1, fmaxf(sc[nt][2], sc[nt][3]));
        }
        #pragma unroll
        for (int off = 1; off < 4; off <<= 1) {
            rmax0 = fmaxf(rmax0, __shfl_xor_sync(0xffffffffu, rmax0, off));
            rmax1 = fmaxf(rmax1, __shfl_xor_sync(0xffffffffu, rmax1, off));
        }
        float mn0 = fmaxf(m_i[0], rmax0);
        float mn1 = fmaxf(m_i[1], rmax1);
        float al0 = ex2((m_i[0] - mn0) * L2E);
        float al1 = ex2((m_i[1] - mn1) * L2E);
        m_i[0] = mn0; m_i[1] = mn1;

        uint32_t ph01[8], ph23[8], pl01[8], pl23[8];
        float rs0 = 0.f, rs1 = 0.f;
        #pragma unroll
        for (int nt = 0; nt < 8; nt++) {
            float p0 = ex2((sc[nt][0] - mn0) * L2E);
            float p1 = ex2((sc[nt][1] - mn0) * L2E);
            float p2 = ex2((sc[nt][2] - mn1) * L2E);
            float p3 = ex2((sc[nt][3] - mn1) * L2E);
            rs0 += p0 + p1; rs1 += p2 + p3;
            __nv_bfloat16 b0 = __float2bfloat16(p0), b1 = __float2bfloat16(p1);
            __nv_bfloat16 b2 = __float2bfloat16(p2), b3 = __float2bfloat16(p3);
            __nv_bfloat162 h01 = __halves2bfloat162(b0, b1);
            __nv_bfloat162 h23 = __halves2bfloat162(b2, b3);
            ph01[nt] = *reinterpret_cast<uint32_t*>(&h01);
            ph23[nt] = *reinterpret_cast<uint32_t*>(&h23);
            pl01[nt] = packbf(p0 - __bfloat162float(b0), p1 - __bfloat162float(b1));
            pl23[nt] = packbf(p2 - __bfloat162float(b2), p3 - __bfloat162float(b3));
        }
        #pragma unroll
        for (int off = 1; off < 4; off <<= 1) {
            rs0 += __shfl_xor_sync(0xffffffffu, rs0, off);
            rs1 += __shfl_xor_sync(0xffffffffu, rs1, off);
        }
        l_i[0] = l_i[0] * al0 + rs0;
        l_i[1] = l_i[1] * al1 + rs1;
        #pragma unroll
        for (int nt = 0; nt < 16; nt++) {
            o[nt][0] *= al0; o[nt][1] *= al0;
            o[nt][2] *= al1; o[nt][3] *= al1;
        }

        // ---- O += P V (3-pass) ----
        #pragma unroll
        for (int kki = 0; kki < 4; kki++) {
            uint32_t aPh[4] = {ph01[2*kki], ph23[2*kki], ph01[2*kki+1], ph23[2*kki+1]};
            uint32_t aPl[4] = {pl01[2*kki], pl23[2*kki], pl01[2*kki+1], pl23[2*kki+1]};
            const int g = lane >> 3, li = lane & 7;
            #pragma unroll
            for (int dj = 0; dj < 8; dj++) {
                uint32_t vh4[4], vl4[4];
                uint32_t voff = (uint32_t)((kki * 16 + (g & 1) * 8 + li) * 272
                                           + (dj * 16 + (g >> 1) * 8) * 2);
                ldsm4t(vh4, vhb + voff);
                ldsm4t(vl4, vlb + voff);
                #pragma unroll
                for (int sel = 0; sel < 2; sel++) {
                    const int nt = dj * 2 + sel;
                    mma16816(o[nt], aPh, vh4[2*sel], vh4[2*sel+1]);
                    mma16816(o[nt], aPh, vl4[2*sel], vl4[2*sel+1]);
                    mma16816(o[nt], aPl, vh4[2*sel], vh4[2*sel+1]);
                }
            }
        }
        __syncthreads();
        if (kt + 2 < nkv) issuekv(kt + 2, buf);
    }

    // ---- epilogue: normalize, split hi/lo, store in blocked att layout ----
    const float inv0 = 1.f / l_i[0];
    const float inv1 = 1.f / l_i[1];
    const int b = bh >> 5, head = bh & 31;
    #pragma unroll
    for (int nt = 0; nt < 16; nt++) {
        const int col = head * 128 + nt * 8 + 2 * (lane & 3);
        const size_t ktb = (size_t)(col >> 5) * BLK_KT_ELEMS + (col & 31);
        #pragma unroll
        for (int hrow = 0; hrow < 2; hrow++) {
            float e  = o[nt][2*hrow]     * (hrow ? inv1 : inv0);
            float od = o[nt][2*hrow + 1] * (hrow ? inv1 : inv0);
            int m = b * S_ + row0 + hrow * 8;
            __nv_bfloat16 he = __float2bfloat16(e);
            __nv_bfloat16 ho = __float2bfloat16(od);
            size_t idx = ktb + (size_t)m * 40;
            *reinterpret_cast<__nv_bfloat162*>(&Oh[idx]) = __halves2bfloat162(he, ho);
            *reinterpret_cast<__nv_bfloat162*>(&Ol[idx]) =
                __halves2bfloat162(__float2bfloat16(e - __bfloat162float(he)),
                                   __float2bfloat16(od - __bfloat162float(ho)));
        }
    }
}

// ---------------------------------------------------------------------------
// Launch.  Order: 0-3 splits, 4-6 GEMMs (ncu -s 5 -> gemm K), 7 split wo,
// 8 attention, 9 output GEMM.
// ---------------------------------------------------------------------------
extern "C" void kernel_launch(void* const* d_in, const int* in_sizes, int n_in,
                              void* d_out, int out_size)
{
    const float* x  = (const float*)d_in[0];
    const float* fc = (const float*)d_in[1];
    const float* fs = (const float*)d_in[2];
    const float* wq = (const float*)d_in[4];
    const float* wk = (const float*)d_in[5];
    const float* wv = (const float*)d_in[6];
    const float* wo = (const float*)d_in[7];
    float* out = (float*)d_out;

    __nv_bfloat16 *xh, *xl, *wqh, *wql, *wkh, *wkl, *wvh, *wvl, *woh, *wol;
    __nv_bfloat16 *qh, *ql, *kh, *kl, *vh, *vl, *ath, *atl;
    cudaGetSymbolAddress((void**)&xh,  g_xh);  cudaGetSymbolAddress((void**)&xl,  g_xl);
    cudaGetSymbolAddress((void**)&wqh, g_wqh); cudaGetSymbolAddress((void**)&wql, g_wql);
    cudaGetSymbolAddress((void**)&wkh, g_wkh); cudaGetSymbolAddress((void**)&wkl, g_wkl);
    cudaGetSymbolAddress((void**)&wvh, g_wvh); cudaGetSymbolAddress((void**)&wvl, g_wvl);
    cudaGetSymbolAddress((void**)&woh, g_woh); cudaGetSymbolAddress((void**)&wol, g_wol);
    cudaGetSymbolAddress((void**)&qh,  g_qh);  cudaGetSymbolAddress((void**)&ql,  g_ql);
    cudaGetSymbolAddress((void**)&kh,  g_kh);  cudaGetSymbolAddress((void**)&kl,  g_kl);
    cudaGetSymbolAddress((void**)&vh,  g_vh);  cudaGetSymbolAddress((void**)&vl,  g_vl);
    cudaGetSymbolAddress((void**)&ath, g_ath); cudaGetSymbolAddress((void**)&atl, g_atl);

    cudaFuncSetAttribute(gemm_mma<0>, cudaFuncAttributeMaxDynamicSharedMemorySize, GEMM_SMEM);
    cudaFuncSetAttribute(gemm_mma<1>, cudaFuncAttributeMaxDynamicSharedMemorySize, GEMM_SMEM);
    cudaFuncSetAttribute(gemm_mma<2>, cudaFuncAttributeMaxDynamicSharedMemorySize, GEMM_SMEM);
    cudaFuncSetAttribute(attn_mma,    cudaFuncAttributeMaxDynamicSharedMemorySize, ATT_SMEM);

    const int n4 = D_ * D_ / 4;
    const dim3 sbk(256), sgd(n4 / 256);
    const dim3 gg(32, 32), gb(256);

    split_blocked<<<sgd, sbk>>>(x,  xh,  xl,  n4);
    split_blocked<<<sgd, sbk>>>(wq, wqh, wql, n4);
    split_blocked<<<sgd, sbk>>>(wk, wkh, wkl, n4);
    split_blocked<<<sgd, sbk>>>(wv, wvh, wvl, n4);
    gemm_mma<2><<<gg, gb, GEMM_SMEM>>>(xh, xl, wqh, wql, nullptr, qh, ql, fc, fs);
    gemm_mma<2><<<gg, gb, GEMM_SMEM>>>(xh, xl, wkh, wkl, nullptr, kh, kl, fc, fs);
    gemm_mma<1><<<gg, gb, GEMM_SMEM>>>(xh, xl, wvh, wvl, nullptr, vh, vl, fc, fs);
    split_blocked<<<sgd, sbk>>>(wo, woh, wol, n4);
    attn_mma<<<dim3(64, 16), 256, ATT_SMEM>>>(qh, ql, kh, kl, vh, vl, ath, atl);
    gemm_mma<0><<<gg, gb, GEMM_SMEM>>>(ath, atl, woh, wol, out, nullptr, nullptr, fc, fs);
}